// round 14
// baseline (speedup 1.0000x reference)
#include <cuda_runtime.h>
#include <cuda_bf16.h>
#include <cuda_fp16.h>

typedef unsigned int u32;
typedef unsigned char u8;
typedef unsigned short u16;

#define ROWS 65536
#define NBSTRIDE 33792
#define MIDB 1088              // padded concat stride (1056 data + 32 zeros)
#define MIN_VAL (-10000000.0f)
#define GRID_P 304

// ---------------- persistent scratch (BSS, zero-init) ----------------
__device__ u8    g_hc [(size_t)ROWS * MIDB];   // fp8: [x(32) | h1..h4 | zeros]
__device__ u8    g_agg[(size_t)ROWS * 256];    // compact aggregated input (e4m3)
__device__ u8    g_w0t[256 * 64];              // W0^T [N=256][K=64], k>=32 zero
__device__ u8    g_wst[3][256 * 256];          // Ws^T fp8
__device__ u8    g_w1t[(size_t)512 * 1088];    // W1^T fp8, k>=1056 zero
__device__ float g_part[2 * ROWS];             // head partial dots per N-half
__device__ float g_sc[512], g_sh[512];         // folded BN scale/shift
__device__ u32   g_ctr[8];                     // dynamic tile counters

// ---------------- helpers ----------------
__device__ __forceinline__ u32 s2u(const void* p){
    u32 a;
    asm("{ .reg .u64 t; cvta.to.shared.u64 t, %1; cvt.u32.u64 %0, t; }" : "=r"(a) : "l"(p));
    return a;
}
__device__ __forceinline__ void cpa16(u32 dst, const void* src){
    asm volatile("cp.async.cg.shared.global [%0], [%1], 16;" :: "r"(dst), "l"(src));
}
#define CP_COMMIT() asm volatile("cp.async.commit_group;" ::: "memory")
#define CP_WAIT(n)  asm volatile("cp.async.wait_group %0;" :: "n"(n) : "memory")

__device__ __forceinline__ void mma_fp8_h(u32* c, const u32* a, const u32* b){
    asm volatile("mma.sync.aligned.m16n8k32.row.col.f16.e4m3.e4m3.f16 "
        "{%0,%1}, {%2,%3,%4,%5}, {%6,%7}, {%0,%1};"
        : "+r"(c[0]), "+r"(c[1])
        : "r"(a[0]), "r"(a[1]), "r"(a[2]), "r"(a[3]), "r"(b[0]), "r"(b[1]));
}
#define LDSM4(r0, r1, r2, r3, addr) \
    asm volatile("ldmatrix.sync.aligned.m8n8.x4.shared.b16 {%0,%1,%2,%3}, [%4];" \
        : "=r"(r0), "=r"(r1), "=r"(r2), "=r"(r3) : "r"(addr))

__device__ __forceinline__ u16 pk8(float lo, float hi){
    u16 t;
    asm("cvt.rn.satfinite.e4m3x2.f32 %0, %1, %2;" : "=h"(t) : "f"(hi), "f"(lo));
    return t;
}
__device__ __forceinline__ u8 cvt1(float v){ return (u8)(pk8(v, 0.f) & 0xff); }
__device__ __forceinline__ float2 h2f(u32 h){
    return __half22float2(*reinterpret_cast<__half2*>(&h));
}
__device__ __forceinline__ void hacc_fp8x4(u32& a0, u32& a1, u32 v){
    u32 f0, f1;
    asm("cvt.rn.f16x2.e4m3x2 %0, %1;" : "=r"(f0) : "h"((u16)(v & 0xffff)));
    asm("cvt.rn.f16x2.e4m3x2 %0, %1;" : "=r"(f1) : "h"((u16)(v >> 16)));
    asm("add.rn.f16x2 %0, %0, %1;" : "+r"(a0) : "r"(f0));
    asm("add.rn.f16x2 %0, %0, %1;" : "+r"(a1) : "r"(f1));
}
__device__ __forceinline__ u32 pack2h(u32 h0, u32 h1){
    u16 a, b;
    asm("cvt.rn.satfinite.e4m3x2.f16x2 %0, %1;" : "=h"(a) : "r"(h0));
    asm("cvt.rn.satfinite.e4m3x2.f16x2 %0, %1;" : "=h"(b) : "r"(h1));
    return (u32)a | ((u32)b << 16);
}

// ---------------- merged prep kernel ----------------
__global__ void prep_all(const float* __restrict__ W0, const float* __restrict__ Ws,
                         const float* __restrict__ W1,
                         const float* __restrict__ bn_g, const float* __restrict__ bn_b,
                         const float* __restrict__ bn_m, const float* __restrict__ bn_v){
    int blk = blockIdx.x, tid = threadIdx.x;
    if (blk < 32){
        int i = blk * 256 + tid;
        int n = i >> 5, k = i & 31;
        g_w0t[n * 64 + k] = cvt1(W0[k * 256 + n]);
    } else if (blk < 800){
        int i = (blk - 32) * 256 + tid;
        int l = i >> 16, r = i & 65535;
        int n = r >> 8, k = r & 255;
        g_wst[l][n * 256 + k] = cvt1(Ws[l * 65536 + k * 256 + n]);
    } else if (blk < 2976){
        int i = (blk - 800) * 256 + tid;
        int n = i / 1088, k = i - n * 1088;
        g_w1t[i] = (k < 1056) ? cvt1(W1[k * 512 + n]) : (u8)0;
    } else {
        int i = (blk - 2976) * 256 + tid;
        if (i < 512){
            float sc = bn_g[i] * rsqrtf(bn_v[i] + 1e-5f);
            g_sc[i] = sc;
            g_sh[i] = bn_b[i] - bn_m[i] * sc;
        }
    }
}

__global__ void xcvt(const float* __restrict__ obs){
    int q = blockIdx.x * 256 + threadIdx.x;
    int row = q >> 2, j = q & 3;
    int b = row >> 10, n = row & 1023;
    const float4* s = reinterpret_cast<const float4*>(obs + (size_t)b * NBSTRIDE + 1024 + n * 32 + j * 8);
    float4 a = s[0], c = s[1];
    u32 w0 = (u32)pk8(a.x, a.y) | ((u32)pk8(a.z, a.w) << 16);
    u32 w1 = (u32)pk8(c.x, c.y) | ((u32)pk8(c.z, c.w) << 16);
    *reinterpret_cast<uint2*>(g_hc + (size_t)row * MIDB + j * 8) = make_uint2(w0, w1);
}

// ---------------- standalone grid 4-neighbor aggregation (e4m3, f16 sums) ----------
// One 16B output segment per thread. KW = output row width, SRCW = valid data width.
template<int KW, int SRCW>
__global__ void agg_k(const u8* __restrict__ src, u8* __restrict__ dst){
    constexpr int SPR = KW / 16;
    int idx = blockIdx.x * 256 + threadIdx.x;       // ROWS * SPR
    int row = idx / SPR, seg = idx - row * SPR;
    int colb = seg * 16;
    u8* d = dst + (size_t)row * KW + colb;
    if (SRCW < KW && colb >= SRCW){
        *reinterpret_cast<uint4*>(d) = make_uint4(0u, 0u, 0u, 0u);
        return;
    }
    int n = row & 1023, r = n >> 5, c = n & 31;
    const u8* base = src + (size_t)row * MIDB + colb;
    u32 s[8];
#pragma unroll
    for (int e = 0; e < 8; e++) s[e] = 0u;
    uint4 v;
    if (c > 0){  v = *reinterpret_cast<const uint4*>(base - MIDB);
        hacc_fp8x4(s[0], s[1], v.x); hacc_fp8x4(s[2], s[3], v.y);
        hacc_fp8x4(s[4], s[5], v.z); hacc_fp8x4(s[6], s[7], v.w); }
    if (c < 31){ v = *reinterpret_cast<const uint4*>(base + MIDB);
        hacc_fp8x4(s[0], s[1], v.x); hacc_fp8x4(s[2], s[3], v.y);
        hacc_fp8x4(s[4], s[5], v.z); hacc_fp8x4(s[6], s[7], v.w); }
    if (r > 0){  v = *reinterpret_cast<const uint4*>(base - 32 * MIDB);
        hacc_fp8x4(s[0], s[1], v.x); hacc_fp8x4(s[2], s[3], v.y);
        hacc_fp8x4(s[4], s[5], v.z); hacc_fp8x4(s[6], s[7], v.w); }
    if (r < 31){ v = *reinterpret_cast<const uint4*>(base + 32 * MIDB);
        hacc_fp8x4(s[0], s[1], v.x); hacc_fp8x4(s[2], s[3], v.y);
        hacc_fp8x4(s[4], s[5], v.z); hacc_fp8x4(s[6], s[7], v.w); }
    *reinterpret_cast<uint4*>(d) =
        make_uint4(pack2h(s[0], s[1]), pack2h(s[2], s[3]),
                   pack2h(s[4], s[5]), pack2h(s[6], s[7]));
}

// ---------------- unified persistent FP8 GEMM: tile 128x256, warp tile 64x64 ----------
// 256 thr, occ 2, 8 warps (wm=wid&1 over 2 M-halves, wn=wid>>1 over 4 N-tiles).
// K chunk = 64 (2 k32 mma). 3-stage. Stage: A 128x80 @0 (10240), B 256x80 (20480) = 30720.
// red @92160 (4KB), musd @96256 (1KB). Total 97280.
#define SMTOT 97280
template<int KFULL, bool LN>
__global__ void __launch_bounds__(256, 2)
gemm_u(const u8* __restrict__ A, int astride, const u8* __restrict__ Bt,
       int slot, int ntiles,
       const float* __restrict__ bias, const float* __restrict__ gamma,
       const float* __restrict__ beta, u8* __restrict__ outp)
{
    extern __shared__ char sm[];
    __shared__ u32 s_tile;
    const u32 sb = s2u(sm);
    const int tid  = threadIdx.x;
    const int lane = tid & 31, wid = tid >> 5;
    const int wm = wid & 1, wn = wid >> 1;
    constexpr int NC = KFULL / 64;

    for (;;){
        __syncthreads();
        if (tid == 0) s_tile = atomicAdd(&g_ctr[slot], 1u);
        __syncthreads();
        const u32 t = s_tile;
        if (t >= (u32)ntiles) break;

        const int row0  = LN ? ((int)t << 7) : ((int)(t >> 1) << 7);
        const int ncol0 = LN ? 0 : ((int)(t & 1) << 8);
        const u8* Bp = Bt + (size_t)ncol0 * KFULL;

        auto cpA = [&](int kc, int stg){
#pragma unroll
            for (int i = 0; i < 2; i++){          // 128 rows x 4 segs = 512
                int q = tid + 256 * i;
                int r = q >> 2, seg = q & 3;
                cpa16(sb + (u32)stg * 30720u + (u32)(r * 80 + seg * 16),
                      A + (size_t)(row0 + r) * astride + kc * 64 + seg * 16);
            }
        };
        auto cpB = [&](int kc, int stg){
#pragma unroll
            for (int i = 0; i < 4; i++){          // 256 rows x 4 segs = 1024
                int q = tid + 256 * i;
                int n = q >> 2, seg = q & 3;
                cpa16(sb + (u32)stg * 30720u + 10240u + (u32)(n * 80 + seg * 16),
                      Bp + (size_t)n * KFULL + kc * 64 + seg * 16);
            }
        };

        u32 acc[4][8][2];
#pragma unroll
        for (int mt = 0; mt < 4; mt++)
#pragma unroll
            for (int nt = 0; nt < 8; nt++){ acc[mt][nt][0] = 0u; acc[mt][nt][1] = 0u; }

#pragma unroll
        for (int p = 0; p < 2; p++){
            if (p < NC){ cpA(p, p); cpB(p, p); }
            CP_COMMIT();
        }

        for (int kc = 0; kc < NC; kc++){
            if (kc + 2 < NC){
                int stg2 = (kc + 2) % 3;
                cpA(kc + 2, stg2); cpB(kc + 2, stg2);
            }
            CP_COMMIT();
            CP_WAIT(2);
            __syncthreads();

            const u32 Ab = sb + (u32)(kc % 3) * 30720u;
            const u32 Bb = Ab + 10240u;
#pragma unroll
            for (int s = 0; s < 2; s++){
                u32 a[4][4], b[8][2];
#pragma unroll
                for (int mt = 0; mt < 4; mt++){
                    u32 addr = Ab + (u32)((wm * 64 + mt * 16 + (lane & 7) + ((lane >> 3) & 1) * 8) * 80
                                          + s * 32 + (lane >> 4) * 16);
                    LDSM4(a[mt][0], a[mt][1], a[mt][2], a[mt][3], addr);
                }
#pragma unroll
                for (int np = 0; np < 4; np++){
                    u32 addr = Bb + (u32)((wn * 64 + (np * 2 + (lane >> 4)) * 8 + (lane & 7)) * 80
                                          + s * 32 + ((lane >> 3) & 1) * 16);
                    LDSM4(b[np * 2][0], b[np * 2][1], b[np * 2 + 1][0], b[np * 2 + 1][1], addr);
                }
#pragma unroll
                for (int mt = 0; mt < 4; mt++)
#pragma unroll
                    for (int nt = 0; nt < 8; nt++)
                        mma_fp8_h(acc[mt][nt], a[mt], b[nt]);
            }
        }
        __syncthreads();

        const int cbase = wn * 64 + (lane & 3) * 2;

        if (LN){
            // pass 1: stats (re-unpack acc; no vf stash -> fits regs)
            float s1[4][2], s2[4][2];
#pragma unroll
            for (int mt = 0; mt < 4; mt++){ s1[mt][0]=0.f; s1[mt][1]=0.f; s2[mt][0]=0.f; s2[mt][1]=0.f; }
#pragma unroll
            for (int mt = 0; mt < 4; mt++)
#pragma unroll
                for (int nt = 0; nt < 8; nt++){
                    int c = cbase + nt * 8;
                    float b0 = __ldg(bias + c), b1v = __ldg(bias + c + 1);
                    float2 p0 = h2f(acc[mt][nt][0]);
                    float2 p1 = h2f(acc[mt][nt][1]);
                    float v0 = p0.x + b0, v1 = p0.y + b1v;
                    float v2 = p1.x + b0, v3 = p1.y + b1v;
                    s1[mt][0] += v0 + v1; s2[mt][0] = fmaf(v0, v0, fmaf(v1, v1, s2[mt][0]));
                    s1[mt][1] += v2 + v3; s2[mt][1] = fmaf(v2, v2, fmaf(v3, v3, s2[mt][1]));
                }
#pragma unroll
            for (int o = 1; o <= 2; o <<= 1)
#pragma unroll
                for (int mt = 0; mt < 4; mt++)
#pragma unroll
                    for (int h = 0; h < 2; h++){
                        s1[mt][h] += __shfl_xor_sync(0xffffffffu, s1[mt][h], o);
                        s2[mt][h] += __shfl_xor_sync(0xffffffffu, s2[mt][h], o);
                    }
            float2* red = reinterpret_cast<float2*>(sm + 92160);
            if ((lane & 3) == 0){
#pragma unroll
                for (int mt = 0; mt < 4; mt++)
#pragma unroll
                    for (int h = 0; h < 2; h++){
                        int r = wm * 64 + mt * 16 + (lane >> 2) + 8 * h;
                        red[r * 4 + wn] = make_float2(s1[mt][h], s2[mt][h]);
                    }
            }
            __syncthreads();
            float2* musd = reinterpret_cast<float2*>(sm + 96256);
            if (tid < 128){
                float S1 = 0.f, S2 = 0.f;
#pragma unroll
                for (int w = 0; w < 4; w++){ float2 v = red[tid * 4 + w]; S1 += v.x; S2 += v.y; }
                float mu = S1 * (1.f / 256.f);
                float rstd = rsqrtf(fmaf(-mu, mu, S2 * (1.f / 256.f)) + 1e-5f);
                musd[tid] = make_float2(mu, rstd);
            }
            __syncthreads();
            // pass 2: normalize + ReLU + e4m3 store (re-unpack acc)
#pragma unroll
            for (int mt = 0; mt < 4; mt++)
#pragma unroll
                for (int h = 0; h < 2; h++){
                    int r = wm * 64 + mt * 16 + (lane >> 2) + 8 * h;
                    float2 ms = musd[r];
                    u8* orow = outp + (size_t)(row0 + r) * MIDB;
#pragma unroll
                    for (int nt = 0; nt < 8; nt++){
                        int c = cbase + nt * 8;
                        float2 p = (h == 0) ? h2f(acc[mt][nt][0]) : h2f(acc[mt][nt][1]);
                        float v0 = p.x + __ldg(bias + c);
                        float v1 = p.y + __ldg(bias + c + 1);
                        float o0 = fmaxf(fmaf((v0 - ms.x) * ms.y, __ldg(gamma + c),     __ldg(beta + c)),     0.f);
                        float o1 = fmaxf(fmaf((v1 - ms.x) * ms.y, __ldg(gamma + c + 1), __ldg(beta + c + 1)), 0.f);
                        *reinterpret_cast<u16*>(orow + c) = pk8(o0, o1);
                    }
                }
        } else {
            // HEAD epilogue: bias -> BN -> ReLU -> dot(W2 slice) -> per-row partial
            float* part = reinterpret_cast<float*>(sm + 92160);   // [128][4]
#pragma unroll
            for (int mt = 0; mt < 4; mt++)
#pragma unroll
                for (int h = 0; h < 2; h++){
                    int r = wm * 64 + mt * 16 + (lane >> 2) + 8 * h;
                    float s = 0.f;
#pragma unroll
                    for (int nt = 0; nt < 8; nt++){
                        int c  = cbase + nt * 8;
                        int gc = ncol0 + c;
                        float2 p = (h == 0) ? h2f(acc[mt][nt][0]) : h2f(acc[mt][nt][1]);
                        float v0 = p.x + __ldg(bias + gc);
                        float v1 = p.y + __ldg(bias + gc + 1);
                        float t0 = fmaxf(fmaf(v0, g_sc[gc],     g_sh[gc]),     0.f);
                        float t1 = fmaxf(fmaf(v1, g_sc[gc + 1], g_sh[gc + 1]), 0.f);
                        s = fmaf(t0, __ldg(gamma + gc), s);
                        s = fmaf(t1, __ldg(gamma + gc + 1), s);
                    }
                    s += __shfl_xor_sync(0xffffffffu, s, 1);
                    s += __shfl_xor_sync(0xffffffffu, s, 2);
                    if ((lane & 3) == 0) part[r * 4 + wn] = s;
                }
            __syncthreads();
            if (tid < 128){
                float S = part[tid * 4] + part[tid * 4 + 1] + part[tid * 4 + 2] + part[tid * 4 + 3];
                g_part[(size_t)(t & 1) * ROWS + row0 + tid] = S;
            }
        }
    }
}

// ---------------- tail: combine partials, +b2, mask; reset counters ----------------
__global__ void mask_kernel(const float* __restrict__ obs, const float* __restrict__ b2,
                            float* __restrict__ out){
    int idx = blockIdx.x * 256 + threadIdx.x;
    int b = idx >> 10, n = idx & 1023;
    float y = g_part[idx] + g_part[ROWS + idx] + b2[0];
    out[idx] = (obs[(size_t)b * NBSTRIDE + n] != 0.f) ? y : MIN_VAL;
    if (idx < 8) g_ctr[idx] = 0u;
}

// ---------------- launch ----------------
extern "C" void kernel_launch(void* const* d_in, const int* in_sizes, int n_in,
                              void* d_out, int out_size) {
    const float* obs  = (const float*)d_in[0];
    const float* W0   = (const float*)d_in[3];
    const float* b0   = (const float*)d_in[4];
    const float* g0   = (const float*)d_in[5];
    const float* be0  = (const float*)d_in[6];
    const float* Ws   = (const float*)d_in[7];
    const float* bs   = (const float*)d_in[8];
    const float* gs   = (const float*)d_in[9];
    const float* bes  = (const float*)d_in[10];
    const float* W1   = (const float*)d_in[11];
    const float* b1   = (const float*)d_in[12];
    const float* bn_g = (const float*)d_in[13];
    const float* bn_b = (const float*)d_in[14];
    const float* bn_m = (const float*)d_in[15];
    const float* bn_v = (const float*)d_in[16];
    const float* W2   = (const float*)d_in[17];
    const float* b2   = (const float*)d_in[18];
    float* out = (float*)d_out;

    u8 *hc, *agg, *w0t, *wst, *w1t;
    cudaGetSymbolAddress((void**)&hc,  g_hc);
    cudaGetSymbolAddress((void**)&agg, g_agg);
    cudaGetSymbolAddress((void**)&w0t, g_w0t);
    cudaGetSymbolAddress((void**)&wst, g_wst);
    cudaGetSymbolAddress((void**)&w1t, g_w1t);

    cudaFuncSetAttribute(gemm_u<64,   true >, cudaFuncAttributeMaxDynamicSharedMemorySize, SMTOT);
    cudaFuncSetAttribute(gemm_u<256,  true >, cudaFuncAttributeMaxDynamicSharedMemorySize, SMTOT);
    cudaFuncSetAttribute(gemm_u<1088, false>, cudaFuncAttributeMaxDynamicSharedMemorySize, SMTOT);

    prep_all<<<2978, 256>>>(W0, Ws, W1, bn_g, bn_b, bn_m, bn_v);
    xcvt<<<1024, 256>>>(obs);

    // Layer 0: agg(x) -> compact 64-wide (cols>=32 zero); h1 = relu(LN(agg @ W0 + b0))
    agg_k<64, 32><<<1024, 256>>>(hc, agg);
    gemm_u<64, true><<<GRID_P, 256, SMTOT>>>(agg, 64, w0t, 0, 512, b0, g0, be0, hc + 32);

    // Layers 1..3: standalone agg -> pure GEMM + LN
    for (int l = 1; l < 4; l++) {
        agg_k<256, 256><<<4096, 256>>>(hc + 32 + (l - 1) * 256, agg);
        gemm_u<256, true><<<GRID_P, 256, SMTOT>>>(
            agg, 256, wst + (size_t)(l - 1) * 65536, l, 512,
            bs + (l - 1) * 256, gs + (l - 1) * 256, bes + (l - 1) * 256,
            hc + 32 + l * 256);
    }

    // Head: fused GEMM + BN + ReLU + W2-dot -> g_part (1024 tiles: 512 M x 2 N)
    gemm_u<1088, false><<<GRID_P, 256, SMTOT>>>(hc, MIDB, w1t, 4, 1024, b1, W2, nullptr, nullptr);

    // Tail: combine + mask + counter reset
    mask_kernel<<<256, 256>>>(obs, b2, out);
}